// round 1
// baseline (speedup 1.0000x reference)
#include <cuda_runtime.h>
#include <cuda_bf16.h>
#include <cstddef>

#define NN 50000
#define NE 1600000
#define DD 128
#define RR 24
#define BB 8
#define KTOT (BB*DD + DD)     /* 1152 */
#define NR (NN*RR)            /* 1,200,000 */

// ---------------- device scratch (no allocations allowed) ----------------
__device__ float g_h0[(size_t)NN * DD];          // embed output / layer1 input
__device__ float g_h1[(size_t)NN * DD];          // relu(layer1 out) = layer2 input
__device__ float g_A [(size_t)NN * KTOT];        // [N, 1152] GEMM LHS
__device__ float g_Wc[(size_t)KTOT * DD];        // [1152, 128] GEMM RHS (bases ++ root)
__device__ int   g_cnt[NR];                      // per (node, relation) edge count
__device__ int   g_tot[NN];                      // per node edge count
__device__ int   g_node_off[NN];                 // exclusive scan of g_tot
__device__ int   g_seg_off[NR];                  // per-seg start (becomes END after placement)
__device__ int   g_sorted_src[NE];               // src indices sorted by (dst*R + type)

// ---------------- kernels ----------------

__global__ void k_embed(const int* __restrict__ x, const float4* __restrict__ emb) {
    int idx = blockIdx.x * blockDim.x + threadIdx.x;     // over NN*32 float4
    if (idx >= NN * 32) return;
    int n = idx >> 5;
    int c = idx & 31;
    ((float4*)g_h0)[idx] = emb[(size_t)x[n] * 32 + c];
}

__global__ void k_zero_cnt() {
    int i = blockIdx.x * blockDim.x + threadIdx.x;
    if (i < NR) g_cnt[i] = 0;
}

__global__ void k_hist(const int* __restrict__ dst, const int* __restrict__ ety) {
    int e = blockIdx.x * blockDim.x + threadIdx.x;
    if (e < NE) atomicAdd(&g_cnt[dst[e] * RR + ety[e]], 1);
}

__global__ void k_node_tot() {
    int n = blockIdx.x * blockDim.x + threadIdx.x;
    if (n >= NN) return;
    const int4* c = (const int4*)&g_cnt[n * RR];   // 24 ints = 6 int4, 16B aligned (n*96B)
    int s = 0;
    #pragma unroll
    for (int j = 0; j < 6; j++) { int4 v = c[j]; s += v.x + v.y + v.z + v.w; }
    g_tot[n] = s;
}

// single-block exclusive scan over 50000 node totals
__global__ void k_scan() {
    __shared__ int wsum[32];
    int tid = threadIdx.x, lane = tid & 31, wid = tid >> 5;
    int carry = 0;
    for (int base = 0; base < NN; base += 1024) {
        int i = base + tid;
        int v = (i < NN) ? g_tot[i] : 0;
        int incl = v;
        #pragma unroll
        for (int d = 1; d < 32; d <<= 1) {
            int t = __shfl_up_sync(0xffffffffu, incl, d);
            if (lane >= d) incl += t;
        }
        if (lane == 31) wsum[wid] = incl;
        __syncthreads();
        if (wid == 0) {
            int w = wsum[lane];
            #pragma unroll
            for (int d = 1; d < 32; d <<= 1) {
                int t = __shfl_up_sync(0xffffffffu, w, d);
                if (lane >= d) w += t;
            }
            wsum[lane] = w;
        }
        __syncthreads();
        int off  = (wid > 0) ? wsum[wid - 1] : 0;
        int btot = wsum[31];
        if (i < NN) g_node_off[i] = carry + off + incl - v;
        __syncthreads();
        carry += btot;
    }
}

__global__ void k_seg_off() {
    int n = blockIdx.x * blockDim.x + threadIdx.x;
    if (n >= NN) return;
    int run = g_node_off[n];
    #pragma unroll
    for (int r = 0; r < RR; r++) {
        g_seg_off[n * RR + r] = run;
        run += g_cnt[n * RR + r];
    }
}

__global__ void k_place(const int* __restrict__ src, const int* __restrict__ dst,
                        const int* __restrict__ ety) {
    int e = blockIdx.x * blockDim.x + threadIdx.x;
    if (e >= NE) return;
    int pos = atomicAdd(&g_seg_off[dst[e] * RR + ety[e]], 1);  // seg_off becomes segment END
    g_sorted_src[pos] = src[e];
}

__global__ void k_wc(const float* __restrict__ bases, const float* __restrict__ root) {
    int i = blockIdx.x * blockDim.x + threadIdx.x;
    if (i < BB * DD * DD)      g_Wc[i] = bases[i];
    else if (i < KTOT * DD)    g_Wc[i] = root[i - BB * DD * DD];
}

// Per-node aggregation: mean per (n,r), contract with comp -> Z[n, b*128+i],
// append h row. One block of 128 threads per node (thread = feature index).
__global__ __launch_bounds__(128) void k_aggregate(int use_h1, const float* __restrict__ comp) {
    const float* __restrict__ h = use_h1 ? g_h1 : g_h0;
    int n = blockIdx.x;
    int t = threadIdx.x;

    __shared__ int   s_end[RR];
    __shared__ int   s_cnt[RR];
    __shared__ float s_comp[RR * BB];
    __shared__ int   s_src[1024];

    if (t < RR) {
        s_end[t] = g_seg_off[n * RR + t];   // END after placement
        s_cnt[t] = g_cnt[n * RR + t];
    }
    for (int j = t; j < RR * BB; j += 128) s_comp[j] = comp[j];
    __syncthreads();

    int start = s_end[0] - s_cnt[0];
    int total = s_end[RR - 1] - start;
    bool use_s = (total <= 1024);
    if (use_s) {
        for (int j = t; j < total; j += 128) s_src[j] = g_sorted_src[start + j];
    }
    __syncthreads();

    float z[BB];
    #pragma unroll
    for (int b = 0; b < BB; b++) z[b] = 0.f;

    for (int r = 0; r < RR; r++) {
        int c = s_cnt[r];
        if (c == 0) continue;
        int e1 = s_end[r];
        int e0 = e1 - c;
        float m = 0.f, m2 = 0.f;
        if (use_s) {
            int e = e0;
            for (; e + 1 < e1; e += 2) {
                m  += __ldg(&h[(size_t)s_src[e - start]     * DD + t]);
                m2 += __ldg(&h[(size_t)s_src[e + 1 - start] * DD + t]);
            }
            if (e < e1) m += __ldg(&h[(size_t)s_src[e - start] * DD + t]);
        } else {
            for (int e = e0; e < e1; e++)
                m += __ldg(&h[(size_t)g_sorted_src[e] * DD + t]);
        }
        m = (m + m2) * (1.0f / (float)c);
        #pragma unroll
        for (int b = 0; b < BB; b++) z[b] = fmaf(s_comp[r * BB + b], m, z[b]);
    }

    float* Arow = &g_A[(size_t)n * KTOT];
    #pragma unroll
    for (int b = 0; b < BB; b++) Arow[b * DD + t] = z[b];
    Arow[BB * DD + t] = h[(size_t)n * DD + t];
}

// SGEMM: out[N,128] = g_A[N,1152] @ g_Wc[1152,128] + bias  (optional relu)
// 128x128 tile, BK=8, 256 threads, 8x8 microtile.
__global__ __launch_bounds__(256, 2) void k_gemm(const float* __restrict__ bias,
                                                 float* __restrict__ outp, int relu) {
    __shared__ float As[8][128];
    __shared__ float Bs[8][128];
    const int tid  = threadIdx.x;
    const int row0 = blockIdx.x * 128;
    const int a_r  = tid >> 1;
    const int a_c  = (tid & 1) * 4;
    const int b_r  = tid >> 5;
    const int b_c  = (tid & 31) * 4;
    const int ty   = tid >> 4;
    const int tx   = tid & 15;

    float acc[8][8];
    #pragma unroll
    for (int i = 0; i < 8; i++)
        #pragma unroll
        for (int j = 0; j < 8; j++) acc[i][j] = 0.f;

    const bool aok = (row0 + a_r) < NN;
    const float* Aptr = g_A + (size_t)(row0 + a_r) * KTOT + a_c;

    for (int k0 = 0; k0 < KTOT; k0 += 8) {
        float4 av = aok ? *(const float4*)(Aptr + k0) : make_float4(0.f, 0.f, 0.f, 0.f);
        As[a_c + 0][a_r] = av.x;
        As[a_c + 1][a_r] = av.y;
        As[a_c + 2][a_r] = av.z;
        As[a_c + 3][a_r] = av.w;
        *(float4*)&Bs[b_r][b_c] = *(const float4*)&g_Wc[(size_t)(k0 + b_r) * DD + b_c];
        __syncthreads();
        #pragma unroll
        for (int k = 0; k < 8; k++) {
            float4 a0 = *(const float4*)&As[k][ty * 8];
            float4 a1 = *(const float4*)&As[k][ty * 8 + 4];
            float4 b0 = *(const float4*)&Bs[k][tx * 8];
            float4 b1 = *(const float4*)&Bs[k][tx * 8 + 4];
            float am[8] = {a0.x, a0.y, a0.z, a0.w, a1.x, a1.y, a1.z, a1.w};
            float bn[8] = {b0.x, b0.y, b0.z, b0.w, b1.x, b1.y, b1.z, b1.w};
            #pragma unroll
            for (int i = 0; i < 8; i++)
                #pragma unroll
                for (int j = 0; j < 8; j++)
                    acc[i][j] = fmaf(am[i], bn[j], acc[i][j]);
        }
        __syncthreads();
    }

    float* dstb = outp ? outp : g_h1;
    #pragma unroll
    for (int i = 0; i < 8; i++) {
        int m = row0 + ty * 8 + i;
        if (m < NN) {
            #pragma unroll
            for (int j = 0; j < 8; j += 4) {
                int c = tx * 8 + j;
                float4 v;
                v.x = acc[i][j + 0] + __ldg(&bias[c + 0]);
                v.y = acc[i][j + 1] + __ldg(&bias[c + 1]);
                v.z = acc[i][j + 2] + __ldg(&bias[c + 2]);
                v.w = acc[i][j + 3] + __ldg(&bias[c + 3]);
                if (relu) {
                    v.x = fmaxf(v.x, 0.f); v.y = fmaxf(v.y, 0.f);
                    v.z = fmaxf(v.z, 0.f); v.w = fmaxf(v.w, 0.f);
                }
                *(float4*)&dstb[(size_t)m * DD + c] = v;
            }
        }
    }
}

// ---------------- host launch ----------------
extern "C" void kernel_launch(void* const* d_in, const int* in_sizes, int n_in,
                              void* d_out, int out_size) {
    const int*   x      = (const int*)  d_in[0];
    const int*   ei     = (const int*)  d_in[1];   // [2, E]
    const int*   ety    = (const int*)  d_in[2];
    const float* emb    = (const float*)d_in[3];
    const float* comp1  = (const float*)d_in[4];
    const float* bases1 = (const float*)d_in[5];
    const float* root1  = (const float*)d_in[6];
    const float* bias1  = (const float*)d_in[7];
    const float* comp2  = (const float*)d_in[8];
    const float* bases2 = (const float*)d_in[9];
    const float* root2  = (const float*)d_in[10];
    const float* bias2  = (const float*)d_in[11];
    const int* src = ei;
    const int* dst = ei + NE;
    float* out = (float*)d_out;

    // embedding lookup
    k_embed<<<(NN * 32 + 255) / 256, 256>>>(x, (const float4*)emb);

    // edge counting sort by (dst*R + type) — shared by both layers
    k_zero_cnt<<<(NR + 255) / 256, 256>>>();
    k_hist    <<<(NE + 255) / 256, 256>>>(dst, ety);
    k_node_tot<<<(NN + 255) / 256, 256>>>();
    k_scan    <<<1, 1024>>>();
    k_seg_off <<<(NN + 255) / 256, 256>>>();
    k_place   <<<(NE + 255) / 256, 256>>>(src, dst, ety);

    const int gemm_blocks = (NN + 127) / 128;

    // layer 1 (relu, write g_h1)
    k_wc       <<<(KTOT * DD + 255) / 256, 256>>>(bases1, root1);
    k_aggregate<<<NN, 128>>>(0, comp1);
    k_gemm     <<<gemm_blocks, 256>>>(bias1, nullptr, 1);

    // layer 2 (no relu, write d_out)
    k_wc       <<<(KTOT * DD + 255) / 256, 256>>>(bases2, root2);
    k_aggregate<<<NN, 128>>>(1, comp2);
    k_gemm     <<<gemm_blocks, 256>>>(bias2, out, 0);
}

// round 2
// speedup vs baseline: 1.5969x; 1.5969x over previous
#include <cuda_runtime.h>
#include <cuda_bf16.h>
#include <cstdint>
#include <cstddef>

#define NN 50000
#define NE 1600000
#define DD 128
#define RR 24
#define BB 8
#define KTOT (BB*DD + DD)     /* 1152 */
#define NR (NN*RR)            /* 1,200,000 */

// ---------------- device scratch (no allocations allowed) ----------------
__device__ float g_h0[(size_t)NN * DD];
__device__ float g_h1[(size_t)NN * DD];
__device__ float g_A [(size_t)NN * KTOT];
__device__ float g_Wc[(size_t)KTOT * DD];
__device__ int   g_cnt[NR];
__device__ int   g_tot[NN];
__device__ int   g_node_off[NN];
__device__ int   g_seg_off[NR];
__device__ int   g_sorted_src[NE];

// round-to-nearest tf32 (zero-mean rounding so mma truncation is exact afterwards)
__device__ __forceinline__ float tf32r(float x) {
    uint32_t u;
    asm("cvt.rna.tf32.f32 %0, %1;" : "=r"(u) : "f"(x));
    return __uint_as_float(u);
}

__device__ __forceinline__ void cp16(void* smem_ptr, const void* gptr, bool pred) {
    uint32_t s = (uint32_t)__cvta_generic_to_shared(smem_ptr);
    int sz = pred ? 16 : 0;
    asm volatile("cp.async.cg.shared.global [%0], [%1], 16, %2;\n"
                 :: "r"(s), "l"(gptr), "r"(sz));
}

// ---------------- setup kernels ----------------

__global__ void k_embed(const int* __restrict__ x, const float4* __restrict__ emb) {
    int idx = blockIdx.x * blockDim.x + threadIdx.x;
    if (idx >= NN * 32) return;
    int n = idx >> 5;
    int c = idx & 31;
    ((float4*)g_h0)[idx] = emb[(size_t)x[n] * 32 + c];
}

__global__ void k_zero_cnt() {
    int i = blockIdx.x * blockDim.x + threadIdx.x;
    if (i < NR) g_cnt[i] = 0;
}

__global__ void k_hist(const int* __restrict__ dst, const int* __restrict__ ety) {
    int e = blockIdx.x * blockDim.x + threadIdx.x;
    if (e < NE) atomicAdd(&g_cnt[dst[e] * RR + ety[e]], 1);
}

__global__ void k_node_tot() {
    int n = blockIdx.x * blockDim.x + threadIdx.x;
    if (n >= NN) return;
    const int4* c = (const int4*)&g_cnt[n * RR];
    int s = 0;
    #pragma unroll
    for (int j = 0; j < 6; j++) { int4 v = c[j]; s += v.x + v.y + v.z + v.w; }
    g_tot[n] = s;
}

__global__ void k_scan() {
    __shared__ int wsum[32];
    int tid = threadIdx.x, lane = tid & 31, wid = tid >> 5;
    int carry = 0;
    for (int base = 0; base < NN; base += 1024) {
        int i = base + tid;
        int v = (i < NN) ? g_tot[i] : 0;
        int incl = v;
        #pragma unroll
        for (int d = 1; d < 32; d <<= 1) {
            int t = __shfl_up_sync(0xffffffffu, incl, d);
            if (lane >= d) incl += t;
        }
        if (lane == 31) wsum[wid] = incl;
        __syncthreads();
        if (wid == 0) {
            int w = wsum[lane];
            #pragma unroll
            for (int d = 1; d < 32; d <<= 1) {
                int t = __shfl_up_sync(0xffffffffu, w, d);
                if (lane >= d) w += t;
            }
            wsum[lane] = w;
        }
        __syncthreads();
        int off  = (wid > 0) ? wsum[wid - 1] : 0;
        int btot = wsum[31];
        if (i < NN) g_node_off[i] = carry + off + incl - v;
        __syncthreads();
        carry += btot;
    }
}

__global__ void k_seg_off() {
    int n = blockIdx.x * blockDim.x + threadIdx.x;
    if (n >= NN) return;
    int run = g_node_off[n];
    #pragma unroll
    for (int r = 0; r < RR; r++) {
        g_seg_off[n * RR + r] = run;
        run += g_cnt[n * RR + r];
    }
}

__global__ void k_place(const int* __restrict__ src, const int* __restrict__ dst,
                        const int* __restrict__ ety) {
    int e = blockIdx.x * blockDim.x + threadIdx.x;
    if (e >= NE) return;
    int pos = atomicAdd(&g_seg_off[dst[e] * RR + ety[e]], 1);
    g_sorted_src[pos] = src[e];
}

__global__ void k_wc(const float* __restrict__ bases, const float* __restrict__ root) {
    int i = blockIdx.x * blockDim.x + threadIdx.x;
    if (i < BB * DD * DD)      g_Wc[i] = tf32r(bases[i]);
    else if (i < KTOT * DD)    g_Wc[i] = tf32r(root[i - BB * DD * DD]);
}

// ---------------- aggregation ----------------
// Per node: per-relation mean of gathered h[src] rows, contracted with comp
// on the fly -> A[n, b*128+i], with h row appended. tf32-rounded outputs.
__global__ __launch_bounds__(128) void k_aggregate(int use_h1, const float* __restrict__ comp) {
    const float* __restrict__ h = use_h1 ? g_h1 : g_h0;
    int n = blockIdx.x;
    int t = threadIdx.x;

    __shared__ int   s_end[RR];
    __shared__ int   s_cnt[RR];
    __shared__ float s_comp[RR * BB];
    __shared__ int   s_src[1024];

    if (t < RR) {
        s_end[t] = g_seg_off[n * RR + t];
        s_cnt[t] = g_cnt[n * RR + t];
    }
    for (int j = t; j < RR * BB; j += 128) s_comp[j] = comp[j];
    __syncthreads();

    int start = s_end[0] - s_cnt[0];
    int total = s_end[RR - 1] - start;
    bool use_s = (total <= 1024);
    if (use_s) {
        for (int j = t; j < total; j += 128) s_src[j] = g_sorted_src[start + j];
    }
    __syncthreads();

    float z[BB];
    #pragma unroll
    for (int b = 0; b < BB; b++) z[b] = 0.f;

    for (int r = 0; r < RR; r++) {
        int c = s_cnt[r];
        if (c == 0) continue;
        int e1 = s_end[r];
        int e0 = e1 - c;
        float m0 = 0.f, m1 = 0.f, m2 = 0.f, m3 = 0.f;
        if (use_s) {
            int off = e0 - start;
            int e = 0;
            for (; e + 3 < c; e += 4) {
                m0 += __ldg(&h[(size_t)s_src[off + e]     * DD + t]);
                m1 += __ldg(&h[(size_t)s_src[off + e + 1] * DD + t]);
                m2 += __ldg(&h[(size_t)s_src[off + e + 2] * DD + t]);
                m3 += __ldg(&h[(size_t)s_src[off + e + 3] * DD + t]);
            }
            for (; e < c; e++)
                m0 += __ldg(&h[(size_t)s_src[off + e] * DD + t]);
        } else {
            int e = e0;
            for (; e + 3 < e1; e += 4) {
                m0 += __ldg(&h[(size_t)g_sorted_src[e]     * DD + t]);
                m1 += __ldg(&h[(size_t)g_sorted_src[e + 1] * DD + t]);
                m2 += __ldg(&h[(size_t)g_sorted_src[e + 2] * DD + t]);
                m3 += __ldg(&h[(size_t)g_sorted_src[e + 3] * DD + t]);
            }
            for (; e < e1; e++)
                m0 += __ldg(&h[(size_t)g_sorted_src[e] * DD + t]);
        }
        float m = ((m0 + m1) + (m2 + m3)) * (1.0f / (float)c);
        #pragma unroll
        for (int b = 0; b < BB; b++) z[b] = fmaf(s_comp[r * BB + b], m, z[b]);
    }

    float* Arow = &g_A[(size_t)n * KTOT];
    #pragma unroll
    for (int b = 0; b < BB; b++) Arow[b * DD + t] = tf32r(z[b]);
    Arow[BB * DD + t] = tf32r(h[(size_t)n * DD + t]);
}

// ---------------- tf32 tensor-core GEMM ----------------
// out[N,128] = g_A[N,1152] @ g_Wc[1152,128] + bias (optional relu)
// BM=64, BN=128, BK=16, 128 threads (4 warps, warp tile 32x64), cp.async 2-stage.
#define GBM 64
#define GBK 16
#define NITER (KTOT / GBK)   /* 72 */

__global__ __launch_bounds__(128) void k_gemm_tc(const float* __restrict__ bias,
                                                 float* __restrict__ outp, int relu) {
    __shared__ float As[2][GBM][20];    // [m][k], stride 20 -> conflict-free frags
    __shared__ float Bs[2][GBK][136];   // [k][n], stride 136 -> conflict-free frags

    const int tid  = threadIdx.x;
    const int wid  = tid >> 5;
    const int lane = tid & 31;
    const int g    = lane >> 2;   // groupID
    const int q    = lane & 3;    // thread-in-group
    const int warp_m = (wid >> 1) * 32;
    const int warp_n = (wid & 1) * 64;
    const int row0 = blockIdx.x * GBM;

    float acc[2][8][4];
    #pragma unroll
    for (int mi = 0; mi < 2; mi++)
        #pragma unroll
        for (int nj = 0; nj < 8; nj++)
            #pragma unroll
            for (int k = 0; k < 4; k++) acc[mi][nj][k] = 0.f;

    // --- async tile loaders ---
    // A tile: 64x16 floats = 256 float4; 2 per thread
    // B tile: 16x128 floats = 512 float4; 4 per thread
    #define LOAD_TILES(K0, BUF)                                                   \
    do {                                                                          \
        _Pragma("unroll")                                                         \
        for (int j = 0; j < 2; j++) {                                             \
            int idx = tid + j * 128;                                              \
            int ar = idx >> 2, ac = (idx & 3) * 4;                                \
            bool ok = (row0 + ar) < NN;                                           \
            const float* src = ok ? &g_A[(size_t)(row0 + ar) * KTOT + (K0) + ac]  \
                                  : &g_A[0];                                      \
            cp16(&As[BUF][ar][ac], src, ok);                                      \
        }                                                                         \
        _Pragma("unroll")                                                         \
        for (int j = 0; j < 4; j++) {                                             \
            int idx = tid + j * 128;                                              \
            int br = idx >> 5, bc = (idx & 31) * 4;                               \
            cp16(&Bs[BUF][br][bc], &g_Wc[(size_t)((K0) + br) * DD + bc], true);   \
        }                                                                         \
    } while (0)

    LOAD_TILES(0, 0);
    asm volatile("cp.async.commit_group;");

    for (int it = 0; it < NITER; it++) {
        const int cur = it & 1;
        const int nxt = cur ^ 1;
        if (it + 1 < NITER) LOAD_TILES((it + 1) * GBK, nxt);
        asm volatile("cp.async.commit_group;");
        asm volatile("cp.async.wait_group 1;");
        __syncthreads();

        #pragma unroll
        for (int s = 0; s < 2; s++) {
            const int kb = s * 8;
            uint32_t af[2][4];
            uint32_t bf[8][2];
            #pragma unroll
            for (int mi = 0; mi < 2; mi++) {
                int m = warp_m + mi * 16 + g;
                af[mi][0] = __float_as_uint(As[cur][m][kb + q]);
                af[mi][1] = __float_as_uint(As[cur][m + 8][kb + q]);
                af[mi][2] = __float_as_uint(As[cur][m][kb + q + 4]);
                af[mi][3] = __float_as_uint(As[cur][m + 8][kb + q + 4]);
            }
            #pragma unroll
            for (int nj = 0; nj < 8; nj++) {
                int n = warp_n + nj * 8 + g;
                bf[nj][0] = __float_as_uint(Bs[cur][kb + q][n]);
                bf[nj][1] = __float_as_uint(Bs[cur][kb + q + 4][n]);
            }
            #pragma unroll
            for (int mi = 0; mi < 2; mi++)
                #pragma unroll
                for (int nj = 0; nj < 8; nj++) {
                    asm volatile(
                        "mma.sync.aligned.m16n8k8.row.col.f32.tf32.tf32.f32 "
                        "{%0,%1,%2,%3}, {%4,%5,%6,%7}, {%8,%9}, {%0,%1,%2,%3};\n"
                        : "+f"(acc[mi][nj][0]), "+f"(acc[mi][nj][1]),
                          "+f"(acc[mi][nj][2]), "+f"(acc[mi][nj][3])
                        : "r"(af[mi][0]), "r"(af[mi][1]), "r"(af[mi][2]), "r"(af[mi][3]),
                          "r"(bf[nj][0]), "r"(bf[nj][1]));
                }
        }
        __syncthreads();
    }

    float* dstb = outp ? outp : g_h1;
    #pragma unroll
    for (int mi = 0; mi < 2; mi++) {
        #pragma unroll
        for (int nj = 0; nj < 8; nj++) {
            int c  = warp_n + nj * 8 + q * 2;
            float b0 = __ldg(&bias[c]);
            float b1 = __ldg(&bias[c + 1]);
            int ra = row0 + warp_m + mi * 16 + g;
            int rb = ra + 8;
            float2 v0, v1;
            v0.x = acc[mi][nj][0] + b0; v0.y = acc[mi][nj][1] + b1;
            v1.x = acc[mi][nj][2] + b0; v1.y = acc[mi][nj][3] + b1;
            if (relu) {
                v0.x = fmaxf(v0.x, 0.f); v0.y = fmaxf(v0.y, 0.f);
                v1.x = fmaxf(v1.x, 0.f); v1.y = fmaxf(v1.y, 0.f);
            }
            if (ra < NN) *(float2*)&dstb[(size_t)ra * DD + c] = v0;
            if (rb < NN) *(float2*)&dstb[(size_t)rb * DD + c] = v1;
        }
    }
}

// ---------------- host launch ----------------
extern "C" void kernel_launch(void* const* d_in, const int* in_sizes, int n_in,
                              void* d_out, int out_size) {
    const int*   x      = (const int*)  d_in[0];
    const int*   ei     = (const int*)  d_in[1];
    const int*   ety    = (const int*)  d_in[2];
    const float* emb    = (const float*)d_in[3];
    const float* comp1  = (const float*)d_in[4];
    const float* bases1 = (const float*)d_in[5];
    const float* root1  = (const float*)d_in[6];
    const float* bias1  = (const float*)d_in[7];
    const float* comp2  = (const float*)d_in[8];
    const float* bases2 = (const float*)d_in[9];
    const float* root2  = (const float*)d_in[10];
    const float* bias2  = (const float*)d_in[11];
    const int* src = ei;
    const int* dst = ei + NE;
    float* out = (float*)d_out;

    k_embed<<<(NN * 32 + 255) / 256, 256>>>(x, (const float4*)emb);

    k_zero_cnt<<<(NR + 255) / 256, 256>>>();
    k_hist    <<<(NE + 255) / 256, 256>>>(dst, ety);
    k_node_tot<<<(NN + 255) / 256, 256>>>();
    k_scan    <<<1, 1024>>>();
    k_seg_off <<<(NN + 255) / 256, 256>>>();
    k_place   <<<(NE + 255) / 256, 256>>>(src, dst, ety);

    const int gemm_blocks = (NN + GBM - 1) / GBM;

    k_wc       <<<(KTOT * DD + 255) / 256, 256>>>(bases1, root1);
    k_aggregate<<<NN, 128>>>(0, comp1);
    k_gemm_tc  <<<gemm_blocks, 128>>>(bias1, nullptr, 1);

    k_wc       <<<(KTOT * DD + 255) / 256, 256>>>(bases2, root2);
    k_aggregate<<<NN, 128>>>(1, comp2);
    k_gemm_tc  <<<gemm_blocks, 128>>>(bias2, out, 0);
}